// round 1
// baseline (speedup 1.0000x reference)
#include <cuda_runtime.h>
#include <math.h>

#define G     1920      // number of graphs = BS*T
#define P     22        // nodes per graph
#define NE    462       // edges per graph = P*(P-1)
#define C1    14
#define C2    16
#define C3    32
#define C4    64
#define C5    152
#define T     120
#define BSZ   16
#define NCLS  17
#define DIMCAP 16
#define CO    272       // conv out channels = DIMCAP*NCLS
#define CK    456       // conv reduced dim = C5*3
#define TB    8         // time steps per conv block

// Scratch (device globals — no allocation allowed)
__device__ float g_pooled[G * C5];      // (1920,152)
__device__ float g_cwT[CK * CO];        // transposed conv weights [(c*3+k)][o]

// ---------------------------------------------------------------------------
// Kernel 0: transpose conv_w (272,152,3) -> cwT[(c*3+k)*272 + o]
// ---------------------------------------------------------------------------
__global__ void k_transpose(const float* __restrict__ cw) {
    int idx = blockIdx.x * blockDim.x + threadIdx.x;
    if (idx < CO * CK) {
        int o  = idx / CK;
        int ck = idx % CK;
        g_cwT[ck * CO + o] = cw[idx];
    }
}

// ---------------------------------------------------------------------------
// GCN layer: hout[r][o] = relu( sum_i A[r][i] * (sum_c hin[i][c]*W[c][o]) + b[o] )
// One thread per output channel o; 22-row accumulator in registers.
// ---------------------------------------------------------------------------
__device__ __forceinline__ void gcn_layer(
    const float* __restrict__ hin, float* __restrict__ hout,
    const float* __restrict__ W, const float* __restrict__ b,
    int Cin, int Cout, const float* __restrict__ sA, int tid)
{
    int o = tid;
    if (o < Cout) {
        float acc[P];
        #pragma unroll
        for (int r = 0; r < P; r++) acc[r] = 0.f;
        for (int c = 0; c < Cin; c++) {
            float w = W[c * Cout + o];           // coalesced across threads, L2-hot
            #pragma unroll
            for (int r = 0; r < P; r++) acc[r] += hin[r * C5 + c] * w;  // broadcast LDS
        }
        float bias = b[o];
        #pragma unroll
        for (int r = 0; r < P; r++) {
            float s = bias;
            #pragma unroll
            for (int i = 0; i < P; i++) s += sA[r * P + i] * acc[i];
            hout[r * C5 + o] = fmaxf(s, 0.f);
        }
    }
    __syncthreads();
}

// ---------------------------------------------------------------------------
// Kernel 1: one block per graph. Builds normalized adjacency, runs 4 GCN
// layers fully in shared memory, mean-pools into g_pooled.
// ---------------------------------------------------------------------------
__global__ void __launch_bounds__(256) k_gcn(
    const float* __restrict__ x,
    const float* __restrict__ edge_attr,
    const float* __restrict__ W1, const float* __restrict__ b1,
    const float* __restrict__ W2, const float* __restrict__ b2,
    const float* __restrict__ W3, const float* __restrict__ b3,
    const float* __restrict__ W4, const float* __restrict__ b4)
{
    __shared__ float sA[P * P];       // normalized adjacency: out[r] = sum_i sA[r][i]*h[i]
    __shared__ float sh0[P * C5];
    __shared__ float sh1[P * C5];
    __shared__ float sdinv[P];

    const int g   = blockIdx.x;
    const int tid = threadIdx.x;

    // --- raw weighted adjacency Wm[i][j] = w(i->j) into sh1 (temp), diag = 1 ---
    for (int e = tid; e < NE; e += 256) {
        int i  = e / (P - 1);
        int jj = e % (P - 1);
        int j  = (jj < i) ? jj : jj + 1;
        sh1[i * P + j] = edge_attr[(g * NE + e) * 5 + 4];
    }
    if (tid < P) sh1[tid * P + tid] = 1.0f;
    __syncthreads();

    // --- degrees (per dst j) and dinv ---
    if (tid < P) {
        float d = 0.f;
        #pragma unroll
        for (int i = 0; i < P; i++) d += sh1[i * P + tid];
        sdinv[tid] = (d > 0.f) ? (1.0f / sqrtf(d)) : 0.f;
    }
    __syncthreads();

    // --- sA[j][i] = dinv[i]*dinv[j]*Wm[i][j] ---
    for (int e = tid; e < P * P; e += 256) {
        int j = e / P, i = e % P;
        sA[j * P + i] = sdinv[i] * sdinv[j] * sh1[i * P + j];
    }

    // --- load x into sh0 ---
    for (int e = tid; e < P * C1; e += 256) {
        int r = e / C1, c = e % C1;
        sh0[r * C5 + c] = x[(g * P + r) * C1 + c];
    }
    __syncthreads();

    gcn_layer(sh0, sh1, W1, b1, C1, C2, sA, tid);
    gcn_layer(sh1, sh0, W2, b2, C2, C3, sA, tid);
    gcn_layer(sh0, sh1, W3, b3, C3, C4, sA, tid);

    // --- layer 4 + mean pool fused ---
    int o = tid;
    if (o < C5) {
        float acc[P];
        #pragma unroll
        for (int r = 0; r < P; r++) acc[r] = 0.f;
        for (int c = 0; c < C4; c++) {
            float w = W4[c * C5 + o];
            #pragma unroll
            for (int r = 0; r < P; r++) acc[r] += sh1[r * C5 + c] * w;
        }
        float bias = b4[o];
        float sum = 0.f;
        #pragma unroll
        for (int r = 0; r < P; r++) {
            float s = bias;
            #pragma unroll
            for (int i = 0; i < P; i++) s += sA[r * P + i] * acc[i];
            sum += fmaxf(s, 0.f);
        }
        g_pooled[g * C5 + o] = sum * (1.0f / 22.0f);
    }
}

// ---------------------------------------------------------------------------
// Kernel 2: conv1d(k=3, pad=1) over T for each batch, + bias + BN-scale +
// sigmoid + capsule norm. One block per (b, 8 time steps).
// out[b,t,n] = sqrt( sum_d (sigmoid(conv[b,d*17+n,t]*scale_t + shift_t)-0.5)^2 / 4 )
// ---------------------------------------------------------------------------
__global__ void __launch_bounds__(288) k_conv(
    const float* __restrict__ conv_b,
    const float* __restrict__ gamma,
    const float* __restrict__ beta,
    float* __restrict__ out)
{
    __shared__ float sp[(TB + 2) * C5];   // feat rows t0-1 .. t0+TB (zero-padded)
    __shared__ float s2[TB * CO];         // (s-0.5)^2 contributions
    __shared__ float sscale[TB], sshift[TB];

    const int b   = blockIdx.x / (T / TB);
    const int t0  = (blockIdx.x % (T / TB)) * TB;
    const int tid = threadIdx.x;

    // load patch (coalesced in c)
    for (int e = tid; e < (TB + 2) * C5; e += 288) {
        int tt = e / C5;                 // 0..TB+1, t = t0+tt-1
        int c  = e % C5;
        int t  = t0 + tt - 1;
        float v = 0.f;
        if (t >= 0 && t < T) v = g_pooled[(b * T + t) * C5 + c];
        sp[tt * C5 + c] = v;
    }
    if (tid < TB) {
        sscale[tid] = gamma[t0 + tid] * (1.0f / sqrtf(1.0f + 0.001f));
        sshift[tid] = beta[t0 + tid];
    }
    __syncthreads();

    int o = tid;
    if (o < CO) {
        float acc[TB];
        #pragma unroll
        for (int tt = 0; tt < TB; tt++) acc[tt] = 0.f;
        for (int c = 0; c < C5; c++) {
            float w0 = g_cwT[(c * 3 + 0) * CO + o];   // coalesced across threads
            float w1 = g_cwT[(c * 3 + 1) * CO + o];
            float w2 = g_cwT[(c * 3 + 2) * CO + o];
            #pragma unroll
            for (int tt = 0; tt < TB; tt++) {
                float p0 = sp[(tt + 0) * C5 + c];     // broadcast LDS
                float p1 = sp[(tt + 1) * C5 + c];
                float p2 = sp[(tt + 2) * C5 + c];
                acc[tt] += p0 * w0 + p1 * w1 + p2 * w2;
            }
        }
        float bias = conv_b[o];
        #pragma unroll
        for (int tt = 0; tt < TB; tt++) {
            float v   = acc[tt] + bias;
            float arg = v * sscale[tt] + sshift[tt];
            float sg  = 1.0f / (1.0f + expf(-arg));
            float d   = sg - 0.5f;
            s2[tt * CO + o] = d * d;
        }
    }
    __syncthreads();

    // capsule norm: reduce 16 dims per (tt, n)
    if (tid < TB * NCLS) {
        int tt = tid / NCLS;
        int n  = tid % NCLS;
        float sum = 0.f;
        #pragma unroll
        for (int d = 0; d < DIMCAP; d++) sum += s2[tt * CO + d * NCLS + n];
        out[(b * T + (t0 + tt)) * NCLS + n] = sqrtf(sum * 0.25f);
    }
}

// ---------------------------------------------------------------------------
// Launch
// ---------------------------------------------------------------------------
extern "C" void kernel_launch(void* const* d_in, const int* in_sizes, int n_in,
                              void* d_out, int out_size) {
    const float* x         = (const float*)d_in[0];
    // d_in[1] = edge_index, d_in[2] = batch: structure is deterministic, unused
    const float* edge_attr = (const float*)d_in[3];
    const float* W1 = (const float*)d_in[4];
    const float* b1 = (const float*)d_in[5];
    const float* W2 = (const float*)d_in[6];
    const float* b2 = (const float*)d_in[7];
    const float* W3 = (const float*)d_in[8];
    const float* b3 = (const float*)d_in[9];
    const float* W4 = (const float*)d_in[10];
    const float* b4 = (const float*)d_in[11];
    const float* conv_w = (const float*)d_in[12];
    const float* conv_bb = (const float*)d_in[13];
    const float* gamma  = (const float*)d_in[14];
    const float* beta   = (const float*)d_in[15];
    float* out = (float*)d_out;

    k_transpose<<<(CO * CK + 255) / 256, 256>>>(conv_w);
    k_gcn<<<G, 256>>>(x, edge_attr, W1, b1, W2, b2, W3, b3, W4, b4);
    k_conv<<<BSZ * (T / TB), 288>>>(conv_bb, gamma, beta, out);
}

// round 2
// speedup vs baseline: 1.0433x; 1.0433x over previous
#include <cuda_runtime.h>
#include <math.h>

#define G     1920
#define P     22
#define NE    462
#define C5    152
#define T     120
#define BSZ   16
#define NCLS  17
#define DIMCAP 16
#define CO    272
#define CK    456
#define HS    152        // h row stride (floats), 608B = 16B aligned
#define TBC   12         // conv time tile
#define NTB   (T / TBC)  // 10
#define TXB   128        // extra blocks for weight transpose

__device__ float g_pooled[G * C5];
__device__ float g_cwT[CK * CO];

typedef unsigned long long u64;

// ---- packed f32x2 helpers (Blackwell FFMA2) --------------------------------
__device__ __forceinline__ u64 dup2(float a) {
    u64 d;
    asm("mov.b64 %0, {%1, %1};" : "=l"(d) : "r"(__float_as_uint(a)));
    return d;
}
__device__ __forceinline__ void fma2(u64& acc, u64 a, u64 b) {
    asm("fma.rn.f32x2 %0, %1, %2, %0;" : "+l"(acc) : "l"(a), "l"(b));
}
__device__ __forceinline__ float2 unpk(u64 v) {
    unsigned lo, hi;
    asm("mov.b64 {%0, %1}, %2;" : "=r"(lo), "=r"(hi) : "l"(v));
    return make_float2(__uint_as_float(lo), __uint_as_float(hi));
}

// ---------------------------------------------------------------------------
// Phase A: q[r][c] = sum_i sA[r][i] * h[i][c]   (tasks = P x cin4)
// ---------------------------------------------------------------------------
__device__ __forceinline__ void phaseA(const float* __restrict__ sh,
                                       float* __restrict__ sq,
                                       const float* __restrict__ sA,
                                       int cin4, int tid)
{
    int ntask = P * cin4;
    for (int t = tid; t < ntask; t += 256) {
        int r  = t / cin4;
        int c4 = t - r * cin4;
        const float* sar = sA + r * P;
        const ulonglong2* hv = (const ulonglong2*)(sh + 4 * c4);
        u64 a0 = 0ULL, a1 = 0ULL;
        #pragma unroll
        for (int i = 0; i < P; i++) {
            u64 ad = dup2(sar[i]);
            ulonglong2 h2 = hv[i * (HS / 4)];
            fma2(a0, ad, h2.x);
            fma2(a1, ad, h2.y);
        }
        ulonglong2 o2; o2.x = a0; o2.y = a1;
        *(ulonglong2*)(sq + r * HS + 4 * c4) = o2;
    }
}

// ---------------------------------------------------------------------------
// Phase B: h'[r][o] = relu(b[o] + sum_c q[r][c]*W[c][o])
// tasks = 11 row-pairs x (COUT/8) o-octets; 2x8 register tile, FFMA2
// ---------------------------------------------------------------------------
template<int CIN, int COUT>
__device__ __forceinline__ void phaseB(const float* __restrict__ sq,
                                       float* __restrict__ sh,
                                       const float* __restrict__ W,
                                       const float* __restrict__ b,
                                       int tid)
{
    const int NO8 = COUT / 8;
    const int NT  = 11 * NO8;
    for (int t = tid; t < NT; t += 256) {
        int rp = t / NO8;
        int o8 = t - rp * NO8;
        const float* q0 = sq + (2 * rp) * HS;
        const float* q1 = q0 + HS;
        u64 acc[2][4] = {{0ULL,0ULL,0ULL,0ULL},{0ULL,0ULL,0ULL,0ULL}};
        #pragma unroll 8
        for (int c = 0; c < CIN; c++) {
            u64 a0 = dup2(q0[c]);
            u64 a1 = dup2(q1[c]);
            const ulonglong2* wp = (const ulonglong2*)(W + c * COUT + o8 * 8);
            ulonglong2 w01 = wp[0];
            ulonglong2 w23 = wp[1];
            fma2(acc[0][0], a0, w01.x); fma2(acc[0][1], a0, w01.y);
            fma2(acc[0][2], a0, w23.x); fma2(acc[0][3], a0, w23.y);
            fma2(acc[1][0], a1, w01.x); fma2(acc[1][1], a1, w01.y);
            fma2(acc[1][2], a1, w23.x); fma2(acc[1][3], a1, w23.y);
        }
        float4 bA = *(const float4*)(b + o8 * 8);
        float4 bB = *(const float4*)(b + o8 * 8 + 4);
        #pragma unroll
        for (int rr = 0; rr < 2; rr++) {
            float2 v0 = unpk(acc[rr][0]);
            float2 v1 = unpk(acc[rr][1]);
            float2 v2 = unpk(acc[rr][2]);
            float2 v3 = unpk(acc[rr][3]);
            float4 sA4, sB4;
            sA4.x = fmaxf(v0.x + bA.x, 0.f);
            sA4.y = fmaxf(v0.y + bA.y, 0.f);
            sA4.z = fmaxf(v1.x + bA.z, 0.f);
            sA4.w = fmaxf(v1.y + bA.w, 0.f);
            sB4.x = fmaxf(v2.x + bB.x, 0.f);
            sB4.y = fmaxf(v2.y + bB.y, 0.f);
            sB4.z = fmaxf(v3.x + bB.z, 0.f);
            sB4.w = fmaxf(v3.y + bB.w, 0.f);
            float* dst = sh + (2 * rp + rr) * HS + o8 * 8;
            *(float4*)(dst)     = sA4;
            *(float4*)(dst + 4) = sB4;
        }
    }
}

// ---------------------------------------------------------------------------
// k_gcn: one block per graph (blocks >= G do the conv weight transpose)
// ---------------------------------------------------------------------------
__global__ void __launch_bounds__(256) k_gcn(
    const float* __restrict__ x,
    const float* __restrict__ edge_attr,
    const float* __restrict__ W1, const float* __restrict__ b1,
    const float* __restrict__ W2, const float* __restrict__ b2,
    const float* __restrict__ W3, const float* __restrict__ b3,
    const float* __restrict__ W4, const float* __restrict__ b4,
    const float* __restrict__ conv_w)
{
    // ---- transpose blocks ----
    if (blockIdx.x >= G) {
        int base = (blockIdx.x - G) * 256 + threadIdx.x;
        for (int idx = base; idx < CK * CO; idx += TXB * 256) {
            int ck = idx / CO;
            int o  = idx - ck * CO;
            g_cwT[idx] = conv_w[o * CK + ck];   // write coalesced
        }
        return;
    }

    __shared__ float sA[P * P];
    __shared__ float sh[P * HS];
    __shared__ float sq[P * HS];
    __shared__ float sdinv[P];

    const int g   = blockIdx.x;
    const int tid = threadIdx.x;

    // raw weighted adjacency Wm[i][j] into sq (temp), diag = 1
    for (int e = tid; e < NE; e += 256) {
        int i  = e / (P - 1);
        int jj = e - i * (P - 1);
        int j  = (jj < i) ? jj : jj + 1;
        sq[i * P + j] = edge_attr[(g * NE + e) * 5 + 4];
    }
    if (tid < P) sq[tid * P + tid] = 1.0f;
    __syncthreads();

    if (tid < P) {
        float d = 0.f;
        #pragma unroll
        for (int i = 0; i < P; i++) d += sq[i * P + tid];
        sdinv[tid] = (d > 0.f) ? rsqrtf(d) : 0.f;
    }
    __syncthreads();

    // sA[j][i] = dinv[i]*dinv[j]*Wm[i][j]  (row = dst)
    for (int e = tid; e < P * P; e += 256) {
        int j = e / P, i = e - j * P;
        sA[j * P + i] = sdinv[i] * sdinv[j] * sq[i * P + j];
    }

    // load x (14 cols) zero-padded to 16
    for (int e = tid; e < P * 16; e += 256) {
        int r = e >> 4, c = e & 15;
        sh[r * HS + c] = (c < 14) ? x[(g * P + r) * 14 + c] : 0.f;
    }
    __syncthreads();

    phaseA(sh, sq, sA, 4, tid);  __syncthreads();
    phaseB<14, 16>(sq, sh, W1, b1, tid); __syncthreads();

    phaseA(sh, sq, sA, 4, tid);  __syncthreads();
    phaseB<16, 32>(sq, sh, W2, b2, tid); __syncthreads();

    phaseA(sh, sq, sA, 8, tid);  __syncthreads();
    phaseB<32, 64>(sq, sh, W3, b3, tid); __syncthreads();

    phaseA(sh, sq, sA, 16, tid); __syncthreads();
    phaseB<64, 152>(sq, sh, W4, b4, tid); __syncthreads();

    // mean pool over 22 rows (38 float4 columns)
    if (tid < 38) {
        u64 s0 = 0ULL, s1 = 0ULL;
        u64 k22 = dup2(1.0f / 22.0f);
        const ulonglong2* hv = (const ulonglong2*)(sh + tid * 4);
        #pragma unroll
        for (int i = 0; i < P; i++) {
            ulonglong2 h2 = hv[i * (HS / 4)];
            fma2(s0, h2.x, k22);
            fma2(s1, h2.y, k22);
        }
        ulonglong2 o2; o2.x = s0; o2.y = s1;
        *(ulonglong2*)(g_pooled + g * C5 + tid * 4) = o2;
    }
}

// ---------------------------------------------------------------------------
// k_conv: conv1d(k=3,pad=1) + bias + BN-scale + sigmoid + capsule norm
// block = (batch b, 12 time steps); 272 compute threads as 136 o-pairs x 2 tt-halves
// ---------------------------------------------------------------------------
__global__ void __launch_bounds__(288) k_conv(
    const float* __restrict__ conv_b,
    const float* __restrict__ gamma,
    const float* __restrict__ beta,
    float* __restrict__ out)
{
    __shared__ float sp[(TBC + 2) * C5];
    __shared__ float s2[TBC * CO];
    __shared__ float sscale[TBC], sshift[TBC];

    const int b   = blockIdx.x / NTB;
    const int t0  = (blockIdx.x - b * NTB) * TBC;
    const int tid = threadIdx.x;

    // load patch rows t0-1 .. t0+TBC (vectorized, zero padded)
    for (int e = tid; e < (TBC + 2) * (C5 / 4); e += 288) {
        int tt = e / (C5 / 4);
        int c4 = e - tt * (C5 / 4);
        int t  = t0 + tt - 1;
        float4 v = make_float4(0.f, 0.f, 0.f, 0.f);
        if (t >= 0 && t < T) v = *(const float4*)(g_pooled + (b * T + t) * C5 + c4 * 4);
        *(float4*)(sp + tt * C5 + c4 * 4) = v;
    }
    if (tid < TBC) {
        sscale[tid] = gamma[t0 + tid] * rsqrtf(1.0f + 0.001f);
        sshift[tid] = beta[t0 + tid];
    }
    __syncthreads();

    if (tid < 272) {
        const int op  = tid % 136;      // o-pair: outputs 2op, 2op+1
        const int th  = tid / 136;      // tt half
        const int tt0 = th * 6;

        u64 acc[6] = {0ULL,0ULL,0ULL,0ULL,0ULL,0ULL};
        for (int c = 0; c < C5; c++) {
            const float* spc = sp + tt0 * C5 + c;
            u64 pd[8];
            #pragma unroll
            for (int j = 0; j < 8; j++) pd[j] = dup2(spc[j * C5]);
            u64 w0 = ((const u64*)(g_cwT + (c * 3 + 0) * CO))[op];
            u64 w1 = ((const u64*)(g_cwT + (c * 3 + 1) * CO))[op];
            u64 w2 = ((const u64*)(g_cwT + (c * 3 + 2) * CO))[op];
            #pragma unroll
            for (int j = 0; j < 6; j++) {
                fma2(acc[j], pd[j],     w0);
                fma2(acc[j], pd[j + 1], w1);
                fma2(acc[j], pd[j + 2], w2);
            }
        }
        float bx = conv_b[2 * op];
        float by = conv_b[2 * op + 1];
        #pragma unroll
        for (int j = 0; j < 6; j++) {
            int tt = tt0 + j;
            float2 v = unpk(acc[j]);
            float sc = sscale[tt], sf = sshift[tt];
            float ax = (v.x + bx) * sc + sf;
            float ay = (v.y + by) * sc + sf;
            float sx = __frcp_rn(1.0f + __expf(-ax)) - 0.5f;
            float sy = __frcp_rn(1.0f + __expf(-ay)) - 0.5f;
            *(float2*)(s2 + tt * CO + 2 * op) = make_float2(sx * sx, sy * sy);
        }
    }
    __syncthreads();

    // capsule norm: reduce 16 dims per (tt, n)
    if (tid < TBC * NCLS) {
        int tt = tid / NCLS;
        int n  = tid - tt * NCLS;
        float sum = 0.f;
        #pragma unroll
        for (int d = 0; d < DIMCAP; d++) sum += s2[tt * CO + d * NCLS + n];
        out[(b * T + t0 + tt) * NCLS + n] = sqrtf(sum * 0.25f);
    }
}

// ---------------------------------------------------------------------------
extern "C" void kernel_launch(void* const* d_in, const int* in_sizes, int n_in,
                              void* d_out, int out_size) {
    const float* x         = (const float*)d_in[0];
    const float* edge_attr = (const float*)d_in[3];
    const float* W1 = (const float*)d_in[4];
    const float* b1 = (const float*)d_in[5];
    const float* W2 = (const float*)d_in[6];
    const float* b2 = (const float*)d_in[7];
    const float* W3 = (const float*)d_in[8];
    const float* b3 = (const float*)d_in[9];
    const float* W4 = (const float*)d_in[10];
    const float* b4 = (const float*)d_in[11];
    const float* conv_w = (const float*)d_in[12];
    const float* conv_bb = (const float*)d_in[13];
    const float* gamma  = (const float*)d_in[14];
    const float* beta   = (const float*)d_in[15];
    float* out = (float*)d_out;

    k_gcn<<<G + TXB, 256>>>(x, edge_attr, W1, b1, W2, b2, W3, b3, W4, b4, conv_w);
    k_conv<<<BSZ * NTB, 288>>>(conv_bb, gamma, beta, out);
}